// round 15
// baseline (speedup 1.0000x reference)
#include <cuda_runtime.h>
#include <math.h>

// GeneralMaxValPool: segment-argmax pooling over COO remap.
// B=4, OLD=262144, NEW=65536, V=64, nnz=262144, BV=256.
// Weighted argmax == raw argmax (weights constant+positive per segment).
// R15 = R14 structure (premultiplied packed offsets, slab c-stream,
// 5 blocks/SM) with default cache policy (measured fastest pairing).

#define OLDN 262144
#define NEWN 65536
#define BB   4
#define VV   64
#define BVN  256
#define NNZ  262144
#define SEGS 16          // segments per block
#define SG   4           // segments per 64-thread group (SEGS/4)
#define PITCH 257        // shared pitch for srow
#define CAPG 128         // per-group capacity (mean ~16, >30 sigma)
#define UF   4           // float4 loads in flight per thread (64B)
#define SENTS 31         // sentinel sid (>= SEGS)
#define OMASK 0x03FFFFFFu

__device__ int g_start[NEWN + 1];

__global__ void seg_start_kernel(const int* __restrict__ row) {
    const int i4 = blockIdx.x * blockDim.x + threadIdx.x;   // 0..NNZ/4-1
    if (i4 >= NNZ / 4) return;
    const int4 r = __ldg(&((const int4*)row)[i4]);
    const int prev = (i4 == 0) ? -1 : __ldg(&row[i4 * 4 - 1]);
    if (r.x != prev) g_start[r.x] = i4 * 4;                 // row dense+sorted
    if (r.y != r.x)  g_start[r.y] = i4 * 4 + 1;
    if (r.z != r.y)  g_start[r.z] = i4 * 4 + 2;
    if (r.w != r.z)  g_start[r.w] = i4 * 4 + 3;
    if (i4 == NNZ / 4 - 1) g_start[NEWN] = NNZ;
}

__global__ void __launch_bounds__(256, 5)
pool_kernel(const float* __restrict__ x,
            const int*   __restrict__ col,
            float* __restrict__ out)
{
    __shared__ unsigned s_pk[4 * CAPG];      // per group: sid<<26 | n*16
    __shared__ int      srow[SEGS * PITCH];  // stores n*16
    __shared__ int      s_start[SEGS + 1];

    const int s0 = blockIdx.x * SEGS;
    const int t  = threadIdx.x;
    const int g  = t >> 6;        // group 0..3
    const int l  = t & 63;        // lane in group
    const int b  = l >> 4;        // 0..3
    const int v4 = l & 15;        // float4 column, v = v4*4..v4*4+3

    if (t <= SEGS) s_start[t] = g_start[s0 + t];
    __syncthreads();

    const int sg0  = g * SG;
    const int gi0  = s_start[sg0];
    const int gcnt = s_start[sg0 + SG] - gi0;
    const bool fits = (gcnt <= CAPG);

    if (fits) {
        unsigned* pk = s_pk + g * CAPG;
        for (int sl = 0; sl < SG; ++sl) {
            const int a = s_start[sg0 + sl];
            const int e = s_start[sg0 + sl + 1];
            for (int i = a + l; i < e; i += 64)
                pk[i - gi0] = ((unsigned)(sg0 + sl) << 26) | ((unsigned)col[i] << 4);
        }
        const int np = (gcnt + UF - 1) / UF * UF;
        for (int j = gcnt + l; j < np; j += 64)
            pk[j] = (unsigned)SENTS << 26;
    }
    __syncthreads();

    const float4* xb4 = (const float4*)(x + (size_t)b * (OLDN * VV)) + v4;
    const size_t out_val_base = ((size_t)b * (NEWN * VV) + (size_t)s0 * VV) / 4 + v4;
    float4* out4 = (float4*)out;

    if (fits) {
        const unsigned* pk = s_pk + g * CAPG;
        const int np = (gcnt + UF - 1) / UF * UF;
        float bw0 = -INFINITY, bw1 = -INFINITY, bw2 = -INFINITY, bw3 = -INFINITY;
        int   bn0 = 0, bn1 = 0, bn2 = 0, bn3 = 0;       // hold n*16
        unsigned cursid = sg0;
        for (int base = 0; base < np; base += UF) {
            unsigned p[UF];
            float4   pv[UF];
            #pragma unroll
            for (int u = 0; u < UF; ++u) p[u] = pk[base + u];       // LDS.32 broadcast
            #pragma unroll
            for (int u = 0; u < UF; ++u)                             // UF LDG.128 in flight
                pv[u] = __ldg(&xb4[p[u] & OMASK]);                   // offset = mask, no IMAD
            #pragma unroll
            for (int u = 0; u < UF; ++u) {
                const unsigned sid = p[u] >> 26;                     // uniform across group
                if (sid != cursid) {
                    if (cursid < SEGS) {
                        out4[out_val_base + cursid * (VV / 4)] =
                            make_float4(bw0, bw1, bw2, bw3);
                        const int sb = (int)cursid * PITCH + b * 64 + v4 * 4;
                        srow[sb + 0] = bn0; srow[sb + 1] = bn1;
                        srow[sb + 2] = bn2; srow[sb + 3] = bn3;
                    }
                    cursid = sid;
                    bw0 = bw1 = bw2 = bw3 = -INFINITY;
                    bn0 = bn1 = bn2 = bn3 = 0;
                }
                const int o16 = (int)(p[u] & OMASK);                 // n*16
                if (pv[u].x > bw0) { bw0 = pv[u].x; bn0 = o16; }     // strict > == min-index tiebreak
                if (pv[u].y > bw1) { bw1 = pv[u].y; bn1 = o16; }
                if (pv[u].z > bw2) { bw2 = pv[u].z; bn2 = o16; }
                if (pv[u].w > bw3) { bw3 = pv[u].w; bn3 = o16; }
            }
        }
        if (cursid < SEGS) {
            out4[out_val_base + cursid * (VV / 4)] = make_float4(bw0, bw1, bw2, bw3);
            const int sb = (int)cursid * PITCH + b * 64 + v4 * 4;
            srow[sb + 0] = bn0; srow[sb + 1] = bn1;
            srow[sb + 2] = bn2; srow[sb + 3] = bn3;
        }
    } else {
        // ---- slow fallback (statistically never taken) ----
        for (int sl = sg0; sl < sg0 + SG; ++sl) {
            float bw0 = -INFINITY, bw1 = -INFINITY, bw2 = -INFINITY, bw3 = -INFINITY;
            int   bn0 = 0, bn1 = 0, bn2 = 0, bn3 = 0;
            for (int i = s_start[sl]; i < s_start[sl + 1]; ++i) {
                const int    o16 = __ldg(&col[i]) * 16;
                const float4 pv  = __ldg(&xb4[o16]);
                if (pv.x > bw0) { bw0 = pv.x; bn0 = o16; }
                if (pv.y > bw1) { bw1 = pv.y; bn1 = o16; }
                if (pv.z > bw2) { bw2 = pv.z; bn2 = o16; }
                if (pv.w > bw3) { bw3 = pv.w; bn3 = o16; }
            }
            out4[out_val_base + (size_t)sl * (VV / 4)] = make_float4(bw0, bw1, bw2, bw3);
            const int sb = sl * PITCH + b * 64 + v4 * 4;
            srow[sb + 0] = bn0; srow[sb + 1] = bn1;
            srow[sb + 2] = bn2; srow[sb + 3] = bn3;
        }
    }
    __syncthreads();

    // Phase 2a: n-stream (data-dependent, block-local). srow holds n*16.
    const size_t OFF1 = (size_t)BB * NEWN * VV;            // 16,777,216
    #pragma unroll
    for (int iter = 0; iter < (BVN * SEGS) / 256; ++iter) {  // 16 iters
        const int idx = iter * 256 + t;                       // 0..4095
        const int c   = idx >> 4;                             // 0..255
        const int sl  = idx & 15;
        const int cb  = c & 3;                                // c = v*B + b
        const int cv  = c >> 2;
        const int tc  = cb * 64 + cv;                         // thread-col of (b,v)
        const size_t o = (size_t)c * NEWN + (size_t)(s0 + sl);
        out[OFF1 + o] = (float)(srow[sl * PITCH + tc] >> 4);
    }

    // Phase 2b: c-stream is address-only -> each block writes a CONTIGUOUS
    // 4096-float slab at OFF2 + blockIdx*4096 (lies within one c = blk>>4).
    const size_t OFF2_4 = ((size_t)BB * NEWN * VV + (size_t)BVN * NEWN) / 4;
    const float fc = (float)(blockIdx.x >> 4);               // 16 slabs per c
    const float4 cvec = make_float4(fc, fc, fc, fc);
    const size_t slab4 = OFF2_4 + (size_t)blockIdx.x * (4096 / 4);
    #pragma unroll
    for (int k = 0; k < 4; ++k)
        out4[slab4 + k * 256 + t] = cvec;
}

extern "C" void kernel_launch(void* const* d_in, const int* in_sizes, int n_in,
                              void* d_out, int out_size) {
    const float* x   = (const float*)d_in[0];
    const int*   row = (const int*)d_in[2];
    const int*   col = (const int*)d_in[3];
    float* out = (float*)d_out;

    seg_start_kernel<<<(NNZ / 4 + 255) / 256, 256>>>(row);
    pool_kernel<<<NEWN / SEGS, 256>>>(x, col, out);
}

// round 16
// speedup vs baseline: 1.0219x; 1.0219x over previous
#include <cuda_runtime.h>
#include <math.h>

// GeneralMaxValPool: segment-argmax pooling over COO remap.
// B=4, OLD=262144, NEW=65536, V=64, nnz=262144, BV=256.
// Weighted argmax == raw argmax (weights constant+positive per segment).
// R16 = R14 (best measured) + address-only slab c-stream hoisted to kernel
// entry so its writes overlap the gather-latency-bound prologue.

#define OLDN 262144
#define NEWN 65536
#define BB   4
#define VV   64
#define BVN  256
#define NNZ  262144
#define SEGS 16          // segments per block
#define SG   4           // segments per 64-thread group (SEGS/4)
#define PITCH 257        // shared pitch for srow
#define CAPG 128         // per-group capacity (mean ~16, >30 sigma)
#define UF   4           // float4 loads in flight per thread (64B)
#define SENTS 31         // sentinel sid (>= SEGS)
#define OMASK 0x03FFFFFFu

__device__ int g_start[NEWN + 1];

__global__ void seg_start_kernel(const int* __restrict__ row) {
    const int i4 = blockIdx.x * blockDim.x + threadIdx.x;   // 0..NNZ/4-1
    if (i4 >= NNZ / 4) return;
    const int4 r = __ldg(&((const int4*)row)[i4]);
    const int prev = (i4 == 0) ? -1 : __ldg(&row[i4 * 4 - 1]);
    if (r.x != prev) g_start[r.x] = i4 * 4;                 // row dense+sorted
    if (r.y != r.x)  g_start[r.y] = i4 * 4 + 1;
    if (r.z != r.y)  g_start[r.z] = i4 * 4 + 2;
    if (r.w != r.z)  g_start[r.w] = i4 * 4 + 3;
    if (i4 == NNZ / 4 - 1) g_start[NEWN] = NNZ;
}

__global__ void __launch_bounds__(256, 5)
pool_kernel(const float* __restrict__ x,
            const int*   __restrict__ col,
            float* __restrict__ out)
{
    __shared__ unsigned s_pk[4 * CAPG];      // per group: sid<<26 | n*16
    __shared__ int      srow[SEGS * PITCH];  // stores n*16
    __shared__ int      s_start[SEGS + 1];

    const int s0 = blockIdx.x * SEGS;
    const int t  = threadIdx.x;
    const int g  = t >> 6;        // group 0..3
    const int l  = t & 63;        // lane in group
    const int b  = l >> 4;        // 0..3
    const int v4 = l & 15;        // float4 column, v = v4*4..v4*4+3

    float4* out4 = (float4*)out;

    // Phase 2b HOISTED: c-stream is address-only (out[OFF2 + c*NEW + s] = c),
    // so each block writes its contiguous 4096-float slab immediately —
    // these stores drain while the block is read-latency-bound below.
    {
        const size_t OFF2_4 = ((size_t)BB * NEWN * VV + (size_t)BVN * NEWN) / 4;
        const float fc = (float)(blockIdx.x >> 4);           // 16 slabs per c
        const float4 cvec = make_float4(fc, fc, fc, fc);
        const size_t slab4 = OFF2_4 + (size_t)blockIdx.x * (4096 / 4);
        #pragma unroll
        for (int k = 0; k < 4; ++k)
            __stcs(&out4[slab4 + k * 256 + t], cvec);
    }

    if (t <= SEGS) s_start[t] = g_start[s0 + t];
    __syncthreads();

    const int sg0  = g * SG;
    const int gi0  = s_start[sg0];
    const int gcnt = s_start[sg0 + SG] - gi0;
    const bool fits = (gcnt <= CAPG);

    if (fits) {
        unsigned* pk = s_pk + g * CAPG;
        for (int sl = 0; sl < SG; ++sl) {
            const int a = s_start[sg0 + sl];
            const int e = s_start[sg0 + sl + 1];
            for (int i = a + l; i < e; i += 64)
                pk[i - gi0] = ((unsigned)(sg0 + sl) << 26) | ((unsigned)col[i] << 4);
        }
        const int np = (gcnt + UF - 1) / UF * UF;
        for (int j = gcnt + l; j < np; j += 64)
            pk[j] = (unsigned)SENTS << 26;
    }
    __syncthreads();

    const float4* xb4 = (const float4*)(x + (size_t)b * (OLDN * VV)) + v4;
    const size_t out_val_base = ((size_t)b * (NEWN * VV) + (size_t)s0 * VV) / 4 + v4;

    if (fits) {
        const unsigned* pk = s_pk + g * CAPG;
        const int np = (gcnt + UF - 1) / UF * UF;
        float bw0 = -INFINITY, bw1 = -INFINITY, bw2 = -INFINITY, bw3 = -INFINITY;
        int   bn0 = 0, bn1 = 0, bn2 = 0, bn3 = 0;       // hold n*16
        unsigned cursid = sg0;
        for (int base = 0; base < np; base += UF) {
            unsigned p[UF];
            float4   pv[UF];
            #pragma unroll
            for (int u = 0; u < UF; ++u) p[u] = pk[base + u];       // LDS.32 broadcast
            #pragma unroll
            for (int u = 0; u < UF; ++u)                             // UF LDG.128.CS in flight
                pv[u] = __ldcs(&xb4[p[u] & OMASK]);                  // offset = mask, no IMAD
            #pragma unroll
            for (int u = 0; u < UF; ++u) {
                const unsigned sid = p[u] >> 26;                     // uniform across group
                if (sid != cursid) {
                    if (cursid < SEGS) {
                        __stcs(&out4[out_val_base + cursid * (VV / 4)],
                               make_float4(bw0, bw1, bw2, bw3));
                        const int sb = (int)cursid * PITCH + b * 64 + v4 * 4;
                        srow[sb + 0] = bn0; srow[sb + 1] = bn1;
                        srow[sb + 2] = bn2; srow[sb + 3] = bn3;
                    }
                    cursid = sid;
                    bw0 = bw1 = bw2 = bw3 = -INFINITY;
                    bn0 = bn1 = bn2 = bn3 = 0;
                }
                const int o16 = (int)(p[u] & OMASK);                 // n*16
                if (pv[u].x > bw0) { bw0 = pv[u].x; bn0 = o16; }     // strict > == min-index tiebreak
                if (pv[u].y > bw1) { bw1 = pv[u].y; bn1 = o16; }
                if (pv[u].z > bw2) { bw2 = pv[u].z; bn2 = o16; }
                if (pv[u].w > bw3) { bw3 = pv[u].w; bn3 = o16; }
            }
        }
        if (cursid < SEGS) {
            __stcs(&out4[out_val_base + cursid * (VV / 4)],
                   make_float4(bw0, bw1, bw2, bw3));
            const int sb = (int)cursid * PITCH + b * 64 + v4 * 4;
            srow[sb + 0] = bn0; srow[sb + 1] = bn1;
            srow[sb + 2] = bn2; srow[sb + 3] = bn3;
        }
    } else {
        // ---- slow fallback (statistically never taken) ----
        for (int sl = sg0; sl < sg0 + SG; ++sl) {
            float bw0 = -INFINITY, bw1 = -INFINITY, bw2 = -INFINITY, bw3 = -INFINITY;
            int   bn0 = 0, bn1 = 0, bn2 = 0, bn3 = 0;
            for (int i = s_start[sl]; i < s_start[sl + 1]; ++i) {
                const int    o16 = __ldg(&col[i]) * 16;
                const float4 pv  = __ldcs(&xb4[o16]);
                if (pv.x > bw0) { bw0 = pv.x; bn0 = o16; }
                if (pv.y > bw1) { bw1 = pv.y; bn1 = o16; }
                if (pv.z > bw2) { bw2 = pv.z; bn2 = o16; }
                if (pv.w > bw3) { bw3 = pv.w; bn3 = o16; }
            }
            __stcs(&out4[out_val_base + (size_t)sl * (VV / 4)],
                   make_float4(bw0, bw1, bw2, bw3));
            const int sb = sl * PITCH + b * 64 + v4 * 4;
            srow[sb + 0] = bn0; srow[sb + 1] = bn1;
            srow[sb + 2] = bn2; srow[sb + 3] = bn3;
        }
    }
    __syncthreads();

    // Phase 2a: n-stream (data-dependent, block-local). srow holds n*16.
    const size_t OFF1 = (size_t)BB * NEWN * VV;            // 16,777,216
    #pragma unroll
    for (int iter = 0; iter < (BVN * SEGS) / 256; ++iter) {  // 16 iters
        const int idx = iter * 256 + t;                       // 0..4095
        const int c   = idx >> 4;                             // 0..255
        const int sl  = idx & 15;
        const int cb  = c & 3;                                // c = v*B + b
        const int cv  = c >> 2;
        const int tc  = cb * 64 + cv;                         // thread-col of (b,v)
        const size_t o = (size_t)c * NEWN + (size_t)(s0 + sl);
        __stcs(&out[OFF1 + o], (float)(srow[sl * PITCH + tc] >> 4));
    }
}

extern "C" void kernel_launch(void* const* d_in, const int* in_sizes, int n_in,
                              void* d_out, int out_size) {
    const float* x   = (const float*)d_in[0];
    const int*   row = (const int*)d_in[2];
    const int*   col = (const int*)d_in[3];
    float* out = (float*)d_out;

    seg_start_kernel<<<(NNZ / 4 + 255) / 256, 256>>>(row);
    pool_kernel<<<NEWN / SEGS, 256>>>(x, col, out);
}

// round 17
// speedup vs baseline: 1.0238x; 1.0019x over previous
#include <cuda_runtime.h>
#include <math.h>

// GeneralMaxValPool: segment-argmax pooling over COO remap.
// B=4, OLD=262144, NEW=65536, V=64, nnz=262144, BV=256.
// Weighted argmax == raw argmax (weights constant+positive per segment).
// R17 = R16 (best) + emit-time int->float conversion for the n-stream
// (srow holds float bits; phase 2a becomes pure LDS->STG).

#define OLDN 262144
#define NEWN 65536
#define BB   4
#define VV   64
#define BVN  256
#define NNZ  262144
#define SEGS 16          // segments per block
#define SG   4           // segments per 64-thread group (SEGS/4)
#define PITCH 257        // shared pitch for srow
#define CAPG 128         // per-group capacity (mean ~16, >30 sigma)
#define UF   4           // float4 loads in flight per thread (64B)
#define SENTS 31         // sentinel sid (>= SEGS)
#define OMASK 0x03FFFFFFu

__device__ int g_start[NEWN + 1];

__global__ void seg_start_kernel(const int* __restrict__ row) {
    const int i4 = blockIdx.x * blockDim.x + threadIdx.x;   // 0..NNZ/4-1
    if (i4 >= NNZ / 4) return;
    const int4 r = __ldg(&((const int4*)row)[i4]);
    const int prev = (i4 == 0) ? -1 : __ldg(&row[i4 * 4 - 1]);
    if (r.x != prev) g_start[r.x] = i4 * 4;                 // row dense+sorted
    if (r.y != r.x)  g_start[r.y] = i4 * 4 + 1;
    if (r.z != r.y)  g_start[r.z] = i4 * 4 + 2;
    if (r.w != r.z)  g_start[r.w] = i4 * 4 + 3;
    if (i4 == NNZ / 4 - 1) g_start[NEWN] = NNZ;
}

__global__ void __launch_bounds__(256, 5)
pool_kernel(const float* __restrict__ x,
            const int*   __restrict__ col,
            float* __restrict__ out)
{
    __shared__ unsigned s_pk[4 * CAPG];      // per group: sid<<26 | n*16
    __shared__ float    srow[SEGS * PITCH];  // stores (float)n, ready to write
    __shared__ int      s_start[SEGS + 1];

    const int s0 = blockIdx.x * SEGS;
    const int t  = threadIdx.x;
    const int g  = t >> 6;        // group 0..3
    const int l  = t & 63;        // lane in group
    const int b  = l >> 4;        // 0..3
    const int v4 = l & 15;        // float4 column, v = v4*4..v4*4+3

    float4* out4 = (float4*)out;

    // Phase 2b HOISTED: c-stream is address-only (out[OFF2 + c*NEW + s] = c) —
    // each block writes its contiguous 4096-float slab immediately so the
    // stores drain while the block is read-latency-bound below.
    {
        const size_t OFF2_4 = ((size_t)BB * NEWN * VV + (size_t)BVN * NEWN) / 4;
        const float fc = (float)(blockIdx.x >> 4);           // 16 slabs per c
        const float4 cvec = make_float4(fc, fc, fc, fc);
        const size_t slab4 = OFF2_4 + (size_t)blockIdx.x * (4096 / 4);
        #pragma unroll
        for (int k = 0; k < 4; ++k)
            __stcs(&out4[slab4 + k * 256 + t], cvec);
    }

    if (t <= SEGS) s_start[t] = g_start[s0 + t];
    __syncthreads();

    const int sg0  = g * SG;
    const int gi0  = s_start[sg0];
    const int gcnt = s_start[sg0 + SG] - gi0;
    const bool fits = (gcnt <= CAPG);

    if (fits) {
        unsigned* pk = s_pk + g * CAPG;
        for (int sl = 0; sl < SG; ++sl) {
            const int a = s_start[sg0 + sl];
            const int e = s_start[sg0 + sl + 1];
            for (int i = a + l; i < e; i += 64)
                pk[i - gi0] = ((unsigned)(sg0 + sl) << 26) | ((unsigned)col[i] << 4);
        }
        const int np = (gcnt + UF - 1) / UF * UF;
        for (int j = gcnt + l; j < np; j += 64)
            pk[j] = (unsigned)SENTS << 26;
    }
    __syncthreads();

    const float4* xb4 = (const float4*)(x + (size_t)b * (OLDN * VV)) + v4;
    const size_t out_val_base = ((size_t)b * (NEWN * VV) + (size_t)s0 * VV) / 4 + v4;

    if (fits) {
        const unsigned* pk = s_pk + g * CAPG;
        const int np = (gcnt + UF - 1) / UF * UF;
        float bw0 = -INFINITY, bw1 = -INFINITY, bw2 = -INFINITY, bw3 = -INFINITY;
        int   bn0 = 0, bn1 = 0, bn2 = 0, bn3 = 0;       // hold n*16
        unsigned cursid = sg0;
        for (int base = 0; base < np; base += UF) {
            unsigned p[UF];
            float4   pv[UF];
            #pragma unroll
            for (int u = 0; u < UF; ++u) p[u] = pk[base + u];       // LDS.32 broadcast
            #pragma unroll
            for (int u = 0; u < UF; ++u)                             // UF LDG.128.CS in flight
                pv[u] = __ldcs(&xb4[p[u] & OMASK]);                  // offset = mask, no IMAD
            #pragma unroll
            for (int u = 0; u < UF; ++u) {
                const unsigned sid = p[u] >> 26;                     // uniform across group
                if (sid != cursid) {
                    if (cursid < SEGS) {
                        __stcs(&out4[out_val_base + cursid * (VV / 4)],
                               make_float4(bw0, bw1, bw2, bw3));
                        const int sb = (int)cursid * PITCH + b * 64 + v4 * 4;
                        srow[sb + 0] = (float)(bn0 >> 4);            // I2F at rare emit site
                        srow[sb + 1] = (float)(bn1 >> 4);
                        srow[sb + 2] = (float)(bn2 >> 4);
                        srow[sb + 3] = (float)(bn3 >> 4);
                    }
                    cursid = sid;
                    bw0 = bw1 = bw2 = bw3 = -INFINITY;
                    bn0 = bn1 = bn2 = bn3 = 0;
                }
                const int o16 = (int)(p[u] & OMASK);                 // n*16
                if (pv[u].x > bw0) { bw0 = pv[u].x; bn0 = o16; }     // strict > == min-index tiebreak
                if (pv[u].y > bw1) { bw1 = pv[u].y; bn1 = o16; }
                if (pv[u].z > bw2) { bw2 = pv[u].z; bn2 = o16; }
                if (pv[u].w > bw3) { bw3 = pv[u].w; bn3 = o16; }
            }
        }
        if (cursid < SEGS) {
            __stcs(&out4[out_val_base + cursid * (VV / 4)],
                   make_float4(bw0, bw1, bw2, bw3));
            const int sb = (int)cursid * PITCH + b * 64 + v4 * 4;
            srow[sb + 0] = (float)(bn0 >> 4);
            srow[sb + 1] = (float)(bn1 >> 4);
            srow[sb + 2] = (float)(bn2 >> 4);
            srow[sb + 3] = (float)(bn3 >> 4);
        }
    } else {
        // ---- slow fallback (statistically never taken) ----
        for (int sl = sg0; sl < sg0 + SG; ++sl) {
            float bw0 = -INFINITY, bw1 = -INFINITY, bw2 = -INFINITY, bw3 = -INFINITY;
            int   bn0 = 0, bn1 = 0, bn2 = 0, bn3 = 0;
            for (int i = s_start[sl]; i < s_start[sl + 1]; ++i) {
                const int    o16 = __ldg(&col[i]) * 16;
                const float4 pv  = __ldcs(&xb4[o16]);
                if (pv.x > bw0) { bw0 = pv.x; bn0 = o16; }
                if (pv.y > bw1) { bw1 = pv.y; bn1 = o16; }
                if (pv.z > bw2) { bw2 = pv.z; bn2 = o16; }
                if (pv.w > bw3) { bw3 = pv.w; bn3 = o16; }
            }
            __stcs(&out4[out_val_base + (size_t)sl * (VV / 4)],
                   make_float4(bw0, bw1, bw2, bw3));
            const int sb = sl * PITCH + b * 64 + v4 * 4;
            srow[sb + 0] = (float)(bn0 >> 4);
            srow[sb + 1] = (float)(bn1 >> 4);
            srow[sb + 2] = (float)(bn2 >> 4);
            srow[sb + 3] = (float)(bn3 >> 4);
        }
    }
    __syncthreads();

    // Phase 2a: n-stream (data-dependent, block-local). srow already holds
    // float values -> pure LDS->STG.
    const size_t OFF1 = (size_t)BB * NEWN * VV;            // 16,777,216
    #pragma unroll
    for (int iter = 0; iter < (BVN * SEGS) / 256; ++iter) {  // 16 iters
        const int idx = iter * 256 + t;                       // 0..4095
        const int c   = idx >> 4;                             // 0..255
        const int sl  = idx & 15;
        const int cb  = c & 3;                                // c = v*B + b
        const int cv  = c >> 2;
        const int tc  = cb * 64 + cv;                         // thread-col of (b,v)
        const size_t o = (size_t)c * NEWN + (size_t)(s0 + sl);
        __stcs(&out[OFF1 + o], srow[sl * PITCH + tc]);
    }
}

extern "C" void kernel_launch(void* const* d_in, const int* in_sizes, int n_in,
                              void* d_out, int out_size) {
    const float* x   = (const float*)d_in[0];
    const int*   row = (const int*)d_in[2];
    const int*   col = (const int*)d_in[3];
    float* out = (float*)d_out;

    seg_start_kernel<<<(NNZ / 4 + 255) / 256, 256>>>(row);
    pool_kernel<<<NEWN / SEGS, 256>>>(x, col, out);
}